// round 2
// baseline (speedup 1.0000x reference)
#include <cuda_runtime.h>

#define N_NODES 50000
#define N_EDGES 800000
#define IN_CH   256
#define HC      128
#define NCAT    384
#define EPS_F   1.000001f

// ---------------- scratch (static device arrays; no allocation) ----------------
__device__ float  g_Wcat[IN_CH * NCAT];                 // [256, 384] = Wl | Wu | Ws
__device__ float  g_xm[3][(size_t)N_NODES * HC];        // 0: x@Wl, 1: x@Wu, 2: (x@Ws)*EPS
__device__ float2 g_alpha[4][N_NODES];                  // [src_l, dst_l, src_u, dst_u][n] = (h0,h1)
__device__ float  g_w[2][N_EDGES];                      // per-edge head-0 softmax weight
__device__ int    g_rp[2][N_NODES + 1];                 // CSR row ptr for lower/upper (tgt sorted)

// ---------------- 1) concat weights ----------------
__global__ void prep_wcat(const float* __restrict__ Wl,
                          const float* __restrict__ Wu,
                          const float* __restrict__ Ws) {
    int i = blockIdx.x * blockDim.x + threadIdx.x;
    if (i >= IN_CH * NCAT) return;
    int k = i / NCAT, c = i % NCAT;
    float v;
    if (c < 128)       v = Wl[k * 128 + c];
    else if (c < 256)  v = Wu[k * 128 + (c - 128)];
    else               v = Ws[k * 128 + (c - 256)];
    g_Wcat[i] = v;
}

// ---------------- 2) row pointers via binary search (tgt arrays are sorted) ----------------
__global__ void rowptr_kernel(const int* __restrict__ ltgt, const int* __restrict__ utgt) {
    int t = blockIdx.x * blockDim.x + threadIdx.x;
    if (t > N_NODES) return;
    #pragma unroll
    for (int s = 0; s < 2; s++) {
        const int* tg = (s == 0) ? ltgt : utgt;
        int lo = 0, hi = N_EDGES;
        while (lo < hi) {
            int mid = (lo + hi) >> 1;
            if (tg[mid] < t) lo = mid + 1; else hi = mid;
        }
        g_rp[s][t] = lo;
    }
}

// ---------------- 3) fused SGEMM: x[50000,256] @ Wcat[256,384] ----------------
#define BM 128
#define BN 64
#define BK 16
#define TM 8
#define TN 4

__global__ __launch_bounds__(256) void gemm_kernel(const float* __restrict__ X) {
    __shared__ float As[BK][BM + 4];
    __shared__ float Bs[BK][BN + 4];

    const int bx = blockIdx.x;          // 0..5  (N tiles)
    const int by = blockIdx.y;          // M tiles
    const int tid = threadIdx.x;
    const int tx = tid & 15, ty = tid >> 4;
    const int m0 = by * BM;

    // A-load mapping: 2 x float4 per thread
    const int ar = tid >> 2;            // 0..63
    const int aq = (tid & 3) * 4;       // k offset within tile
    // B-load mapping: 1 x float4 per thread
    const int bk = tid >> 4;            // 0..15
    const int bn = (tid & 15) * 4;

    float acc[TM][TN] = {};

    for (int k0 = 0; k0 < IN_CH; k0 += BK) {
        #pragma unroll
        for (int r = 0; r < 2; r++) {
            int m = m0 + ar + r * 64;
            float4 v = make_float4(0.f, 0.f, 0.f, 0.f);
            if (m < N_NODES)
                v = *(const float4*)(X + (size_t)m * IN_CH + k0 + aq);
            As[aq + 0][ar + r * 64] = v.x;
            As[aq + 1][ar + r * 64] = v.y;
            As[aq + 2][ar + r * 64] = v.z;
            As[aq + 3][ar + r * 64] = v.w;
        }
        *(float4*)&Bs[bk][bn] = *(const float4*)(g_Wcat + (size_t)(k0 + bk) * NCAT + bx * BN + bn);
        __syncthreads();

        #pragma unroll
        for (int k = 0; k < BK; k++) {
            float a[TM], b[TN];
            #pragma unroll
            for (int i = 0; i < TM; i++) a[i] = As[k][ty * TM + i];
            #pragma unroll
            for (int j = 0; j < TN; j++) b[j] = Bs[k][tx * TN + j];
            #pragma unroll
            for (int i = 0; i < TM; i++)
                #pragma unroll
                for (int j = 0; j < TN; j++)
                    acc[i][j] = fmaf(a[i], b[j], acc[i][j]);
        }
        __syncthreads();
    }

    // epilogue: route columns to the right matrix; scale skip by EPS
    const int cg0 = bx * BN + tx * TN;     // global col 0..383 (stays in one 128-block)
    const int mat = cg0 >> 7;
    const int lc  = cg0 & 127;
    const float scale = (mat == 2) ? EPS_F : 1.0f;
    float* dst = g_xm[mat];
    #pragma unroll
    for (int i = 0; i < TM; i++) {
        int m = m0 + ty * TM + i;
        if (m < N_NODES) {
            float4 v = make_float4(acc[i][0] * scale, acc[i][1] * scale,
                                   acc[i][2] * scale, acc[i][3] * scale);
            *(float4*)(dst + (size_t)m * HC + lc) = v;
        }
    }
}

// ---------------- 4) per-node attention logits (leaky_relu(xm . a)) ----------------
__global__ void alpha_kernel(const float* __restrict__ asl, const float* __restrict__ adl,
                             const float* __restrict__ asu, const float* __restrict__ adu) {
    int idx = blockIdx.x * blockDim.x + threadIdx.x;
    if (idx >= N_NODES * 8) return;
    int n = idx >> 3;
    int j = idx & 7;
    int set = j >> 2;          // 0 lower, 1 upper
    int typ = (j >> 1) & 1;    // 0 src, 1 dst
    int h   = j & 1;
    const float* a  = (set == 0) ? (typ == 0 ? asl : adl) : (typ == 0 ? asu : adu);
    const float* xr = g_xm[set] + (size_t)n * HC + h * 64;
    const float* ar = a + h * 64;
    float s = 0.f;
    #pragma unroll
    for (int c = 0; c < 64; c += 4) {
        float4 xv = *(const float4*)(xr + c);
        float4 av = *(const float4*)(ar + c);
        s += xv.x * av.x + xv.y * av.y + xv.z * av.z + xv.w * av.w;
    }
    s = (s > 0.f) ? s : 0.01f * s;   // leaky_relu
    float* slot = (float*)&g_alpha[set * 2 + typ][n];
    slot[h] = s;
}

// ---------------- 5) per-edge head-softmax weight (2 heads -> sigmoid) ----------------
// edge vals cancel (constant over the heads axis). w0 = 1/(1+exp(s1-s0)); w1 = 1-w0.
__global__ void edgew_kernel(const int* __restrict__ lsrc, const int* __restrict__ ltgt,
                             const int* __restrict__ usrc, const int* __restrict__ utgt) {
    int idx = blockIdx.x * blockDim.x + threadIdx.x;
    if (idx >= 2 * N_EDGES) return;
    int s = (idx >= N_EDGES) ? 1 : 0;
    int e = idx - s * N_EDGES;
    const int* src = s ? usrc : lsrc;
    const int* tgt = s ? utgt : ltgt;
    float2 as = g_alpha[s * 2][src[e]];
    float2 at = g_alpha[s * 2 + 1][tgt[e]];
    float d = (as.y + at.y) - (as.x + at.x);      // s1 - s0
    g_w[s][e] = 1.f / (1.f + __expf(d));
}

// ---------------- 6) fused aggregation: warp per target node, both edge sets ----------------
__global__ __launch_bounds__(256) void out_kernel(const int* __restrict__ lsrc,
                                                  const int* __restrict__ usrc,
                                                  float* __restrict__ out) {
    int warp = (blockIdx.x * blockDim.x + threadIdx.x) >> 5;
    int lane = threadIdx.x & 31;
    if (warp >= N_NODES) return;
    const int t = warp;
    const int head = lane >> 4;          // lanes 0-15 head0 (c 0..63), 16-31 head1

    float4 acc = *(const float4*)(g_xm[2] + (size_t)t * HC + lane * 4);   // skip (already *EPS)

    #pragma unroll
    for (int s = 0; s < 2; s++) {
        const int*   src = (s == 0) ? lsrc : usrc;
        const float* xm  = g_xm[s];
        const float* wv  = g_w[s];
        const int beg = g_rp[s][t], end = g_rp[s][t + 1];
        for (int e = beg; e < end; e++) {
            int   sn = src[e];
            float w0 = wv[e];
            float w  = head ? (1.f - w0) : w0;
            float4 v = *(const float4*)(xm + (size_t)sn * HC + lane * 4);
            acc.x = fmaf(v.x, w, acc.x);
            acc.y = fmaf(v.y, w, acc.y);
            acc.z = fmaf(v.z, w, acc.z);
            acc.w = fmaf(v.w, w, acc.w);
        }
    }
    acc.x = fmaxf(acc.x, 0.f);
    acc.y = fmaxf(acc.y, 0.f);
    acc.z = fmaxf(acc.z, 0.f);
    acc.w = fmaxf(acc.w, 0.f);
    *(float4*)(out + (size_t)t * HC + lane * 4) = acc;
}

// ---------------- launcher ----------------
extern "C" void kernel_launch(void* const* d_in, const int* in_sizes, int n_in,
                              void* d_out, int out_size) {
    const float* x    = (const float*)d_in[0];
    const int*   ltgt = (const int*)  d_in[1];
    const int*   lsrc = (const int*)  d_in[2];
    // d_in[3] lower_vals: unused (cancels in head-axis softmax)
    const int*   utgt = (const int*)  d_in[4];
    const int*   usrc = (const int*)  d_in[5];
    // d_in[6] upper_vals: unused
    const float* Wl   = (const float*)d_in[7];
    const float* asl  = (const float*)d_in[8];
    const float* adl  = (const float*)d_in[9];
    const float* Wu   = (const float*)d_in[10];
    const float* asu  = (const float*)d_in[11];
    const float* adu  = (const float*)d_in[12];
    const float* Ws   = (const float*)d_in[13];
    float* out = (float*)d_out;

    prep_wcat<<<(IN_CH * NCAT + 255) / 256, 256>>>(Wl, Wu, Ws);
    rowptr_kernel<<<(N_NODES + 1 + 255) / 256, 256>>>(ltgt, utgt);

    dim3 ggrid(NCAT / BN, (N_NODES + BM - 1) / BM);
    gemm_kernel<<<ggrid, 256>>>(x);

    alpha_kernel<<<(N_NODES * 8 + 255) / 256, 256>>>(asl, adl, asu, adu);
    edgew_kernel<<<(2 * N_EDGES + 255) / 256, 256>>>(lsrc, ltgt, usrc, utgt);

    out_kernel<<<(N_NODES * 32 + 255) / 256, 256>>>(lsrc, usrc, out);
}